// round 1
// baseline (speedup 1.0000x reference)
#include <cuda_runtime.h>
#include <math.h>

#define N_BATCH 16
#define CH 64
#define SCH 128
#define L_IN 8192
#define L_OUT 7682
#define TILE 64
#define NTH 256
#define NUM_BLOCKS 16

// Ping-pong residual buffers (allocation-free scratch).
__device__ float g_bufA[(size_t)N_BATCH * CH * L_IN];
__device__ float g_bufB[(size_t)N_BATCH * CH * L_IN];

// Shared memory layout (float offsets), 32768 floats = 128 KB dynamic smem.
#define OFF_WD 0      // [o][i][tap]  64*64*2 = 8192   (reused as skip staging [s][l] 128*64)
#define OFF_WR 8192   // [o][i]       64*64   = 4096
#define OFF_WS 12288  // [s][i]       128*64  = 8192
#define OFF_X0 20480  // [i][l]       64*64   = 4096   (reused as res staging [c][l])
#define OFF_X1 24576  // [i][l]       64*64   = 4096
#define OFF_G 28672   // [i][l]       64*64   = 4096
#define SMEM_FLOATS 32768

// g = tanh(y) * sigmoid(y), via a = e^{-y}:
// tanh = (1-a^2)/(1+a^2), sigmoid = 1/(1+a). Clamp keeps a^2 finite.
__device__ __forceinline__ float gated(float y) {
    float yc = fminf(fmaxf(y, -15.f), 15.f);
    float a = __expf(-yc);
    float a2 = a * a;
    return __fdividef(1.f - a2, (1.f + a2) * (1.f + a));
}

__global__ void __launch_bounds__(NTH, 1)
wavenet_block_kernel(const float* __restrict__ src, int src_stride,
                     float* __restrict__ dst, int dst_stride,
                     const float* __restrict__ Wd,
                     const float* __restrict__ Wr,
                     const float* __restrict__ Ws,
                     float* __restrict__ skip,
                     int Lcur, int d, int skip_off, int is_first)
{
    extern __shared__ float sm[];
    const int tid = threadIdx.x;
    const int n = blockIdx.y;
    const int l0 = blockIdx.x * TILE;
    const int Lnew = Lcur - d;

    // ---- stage weights (straight coalesced copies) ----
    for (int idx = tid; idx < CH * CH * 2; idx += NTH) sm[OFF_WD + idx] = Wd[idx];
    for (int idx = tid; idx < CH * CH; idx += NTH)     sm[OFF_WR + idx] = Wr[idx];
    for (int idx = tid; idx < SCH * CH; idx += NTH)    sm[OFF_WS + idx] = Ws[idx];

    // ---- stage the two input taps: X0[i][l]=src[l0+l], X1[i][l]=src[l0+l+d] ----
    const float* srcn = src + (size_t)n * CH * src_stride;
    for (int idx = tid; idx < CH * TILE; idx += NTH) {
        int i = idx >> 6, l = idx & 63;
        int p0 = l0 + l;
        int p1 = p0 + d;
        sm[OFF_X0 + idx] = (p0 < Lcur) ? srcn[(size_t)i * src_stride + p0] : 0.f;
        sm[OFF_X1 + idx] = (p1 < Lcur) ? srcn[(size_t)i * src_stride + p1] : 0.f;
    }
    __syncthreads();

    const int lt = (tid & 15) * 4;   // 4 consecutive positions
    const int ot = (tid >> 4) * 4;   // 4 consecutive output channels

    // ================= phase 1: dilated conv (64x64x2) + gated activation =================
    float acc[4][4];
#pragma unroll
    for (int a = 0; a < 4; a++)
#pragma unroll
        for (int b = 0; b < 4; b++) acc[a][b] = 0.f;

    for (int ii = 0; ii < CH; ii += 4) {
        float xa[4][4], xb[4][4];
#pragma unroll
        for (int j = 0; j < 4; j++) {
            *(float4*)xa[j] = *(const float4*)(sm + OFF_X0 + (ii + j) * TILE + lt);
            *(float4*)xb[j] = *(const float4*)(sm + OFF_X1 + (ii + j) * TILE + lt);
        }
#pragma unroll
        for (int oo = 0; oo < 4; oo++) {
            float w[8];
            *(float4*)(w)     = *(const float4*)(sm + OFF_WD + (ot + oo) * (2 * CH) + ii * 2);
            *(float4*)(w + 4) = *(const float4*)(sm + OFF_WD + (ot + oo) * (2 * CH) + ii * 2 + 4);
#pragma unroll
            for (int j = 0; j < 4; j++)
#pragma unroll
                for (int ll = 0; ll < 4; ll++)
                    acc[oo][ll] += w[2 * j] * xa[j][ll] + w[2 * j + 1] * xb[j][ll];
        }
    }
    // gated activation -> sG[o][l]
#pragma unroll
    for (int oo = 0; oo < 4; oo++) {
        float g[4];
#pragma unroll
        for (int ll = 0; ll < 4; ll++) g[ll] = gated(acc[oo][ll]);
        *(float4*)(sm + OFF_G + (ot + oo) * TILE + lt) = *(float4*)g;
    }
    __syncthreads();

    // ================= phase 2a: residual 1x1 conv + residual add =================
    float r[4][4];
#pragma unroll
    for (int a = 0; a < 4; a++)
#pragma unroll
        for (int b = 0; b < 4; b++) r[a][b] = 0.f;

    for (int ii = 0; ii < CH; ii += 4) {
        float gg[4][4];
#pragma unroll
        for (int j = 0; j < 4; j++)
            *(float4*)gg[j] = *(const float4*)(sm + OFF_G + (ii + j) * TILE + lt);
#pragma unroll
        for (int oo = 0; oo < 4; oo++) {
            float w[4];
            *(float4*)w = *(const float4*)(sm + OFF_WR + (ot + oo) * CH + ii);
#pragma unroll
            for (int j = 0; j < 4; j++)
#pragma unroll
                for (int ll = 0; ll < 4; ll++)
                    r[oo][ll] += w[j] * gg[j][ll];
        }
    }
    // residual add (out[:, :, -Lnew:] == tap-1 tile), stage into X0 region
#pragma unroll
    for (int oo = 0; oo < 4; oo++) {
        float o4[4];
#pragma unroll
        for (int ll = 0; ll < 4; ll++)
            o4[ll] = r[oo][ll] + sm[OFF_X1 + (ot + oo) * TILE + lt + ll];
        *(float4*)(sm + OFF_X0 + (ot + oo) * TILE + lt) = *(float4*)o4;
    }

    // ================= phase 2b: skip 1x1 conv (128x64) =================
    const int st = (tid >> 4) * 8;   // 8 skip channels per thread group
    float sk[8][4];
#pragma unroll
    for (int a = 0; a < 8; a++)
#pragma unroll
        for (int b = 0; b < 4; b++) sk[a][b] = 0.f;

    for (int ii = 0; ii < CH; ii += 4) {
        float gg[4][4];
#pragma unroll
        for (int j = 0; j < 4; j++)
            *(float4*)gg[j] = *(const float4*)(sm + OFF_G + (ii + j) * TILE + lt);
#pragma unroll
        for (int ss = 0; ss < 8; ss++) {
            float w[4];
            *(float4*)w = *(const float4*)(sm + OFF_WS + (st + ss) * CH + ii);
#pragma unroll
            for (int j = 0; j < 4; j++)
#pragma unroll
                for (int ll = 0; ll < 4; ll++)
                    sk[ss][ll] += w[j] * gg[j][ll];
        }
    }
    // stage skip into WD region [s][l]
#pragma unroll
    for (int ss = 0; ss < 8; ss++)
        *(float4*)(sm + OFF_WD + (st + ss) * TILE + lt) = *(float4*)sk[ss];

    __syncthreads();

    // ================= coalesced global stores =================
    // residual output: dst[n][c][l0+l]
    for (int idx = tid; idx < CH * TILE; idx += NTH) {
        int c = idx >> 6, l = idx & 63;
        int p = l0 + l;
        if (p < Lnew)
            dst[((size_t)n * CH + c) * dst_stride + p] = sm[OFF_X0 + idx];
    }
    // skip accumulation: skip[n][s][p - skip_off]
    if (is_first) {
        for (int idx = tid; idx < SCH * TILE; idx += NTH) {
            int s = idx >> 6, l = idx & 63;
            int p = l0 + l;
            int j = p - skip_off;
            if (p < Lnew && j >= 0)
                skip[((size_t)n * SCH + s) * L_OUT + j] = sm[OFF_WD + idx];
        }
    } else {
        for (int idx = tid; idx < SCH * TILE; idx += NTH) {
            int s = idx >> 6, l = idx & 63;
            int p = l0 + l;
            int j = p - skip_off;
            if (p < Lnew && j >= 0) {
                size_t gi = ((size_t)n * SCH + s) * L_OUT + j;
                skip[gi] += sm[OFF_WD + idx];
            }
        }
    }
}

extern "C" void kernel_launch(void* const* d_in, const int* in_sizes, int n_in,
                              void* d_out, int out_size)
{
    const float* x  = (const float*)d_in[0];  // (16, 64, 8192)
    const float* Wd = (const float*)d_in[1];  // (16, 64, 64, 2)
    const float* Wr = (const float*)d_in[2];  // (16, 64, 64)
    const float* Ws = (const float*)d_in[3];  // (16, 128, 64)

    float* out  = (float*)d_out;                                   // (16, 64, 7682)
    float* skip = (float*)d_out + (size_t)N_BATCH * CH * L_OUT;    // (16, 128, 7682)

    float *bufA = nullptr, *bufB = nullptr;
    cudaGetSymbolAddress((void**)&bufA, g_bufA);
    cudaGetSymbolAddress((void**)&bufB, g_bufB);
    cudaFuncSetAttribute(wavenet_block_kernel,
                         cudaFuncAttributeMaxDynamicSharedMemorySize,
                         SMEM_FLOATS * (int)sizeof(float));

    const int dil[NUM_BLOCKS] = {1, 2, 4, 8, 16, 32, 64, 128,
                                 1, 2, 4, 8, 16, 32, 64, 128};

    const float* src = x;
    int src_stride = L_IN;
    int Lcur = L_IN;

    for (int i = 0; i < NUM_BLOCKS; i++) {
        int d = dil[i];
        int Lnew = Lcur - d;
        float* dst;
        int dst_stride;
        if (i == NUM_BLOCKS - 1) { dst = out; dst_stride = L_OUT; }
        else                     { dst = (i & 1) ? bufB : bufA; dst_stride = L_IN; }

        dim3 grid((Lnew + TILE - 1) / TILE, N_BATCH);
        wavenet_block_kernel<<<grid, NTH, SMEM_FLOATS * sizeof(float)>>>(
            src, src_stride, dst, dst_stride,
            Wd + (size_t)i * CH * CH * 2,
            Wr + (size_t)i * CH * CH,
            Ws + (size_t)i * SCH * CH,
            skip, Lcur, d, Lnew - L_OUT, (i == 0) ? 1 : 0);

        src = dst;
        src_stride = dst_stride;
        Lcur = Lnew;
    }
}

// round 2
// speedup vs baseline: 2.7248x; 2.7248x over previous
#include <cuda_runtime.h>
#include <math.h>

#define N_BATCH 16
#define CH 64
#define SCH 128
#define L_IN 8192
#define L_OUT 7682
#define TILE 128
#define NTH 512
#define NUM_BLOCKS 16

// Ping-pong residual buffers (allocation-free scratch).
__device__ float g_bufA[(size_t)N_BATCH * CH * L_IN];
__device__ float g_bufB[(size_t)N_BATCH * CH * L_IN];

// Shared memory: only activations. 3 * 64 * 128 floats = 96 KB -> 2 CTAs/SM.
#define OFF_X0 0
#define OFF_X1 (CH * TILE)
#define OFF_G  (2 * CH * TILE)
#define SMEM_FLOATS (3 * CH * TILE)

// g = tanh(y) * sigmoid(y), via a = e^{-y}:
// tanh = (1-a^2)/(1+a^2), sigmoid = 1/(1+a). Clamp keeps a^2 finite.
__device__ __forceinline__ float gated(float y) {
    float yc = fminf(fmaxf(y, -15.f), 15.f);
    float a = __expf(-yc);
    float a2 = a * a;
    return __fdividef(1.f - a2, (1.f + a2) * (1.f + a));
}

__global__ void __launch_bounds__(NTH, 2)
wavenet_block_kernel(const float* __restrict__ src, int src_stride,
                     float* __restrict__ dst, int dst_stride,
                     const float* __restrict__ Wd,
                     const float* __restrict__ Wr,
                     const float* __restrict__ Ws,
                     float* __restrict__ skip,
                     int Lcur, int d, int skip_off, int is_first)
{
    extern __shared__ float sm[];
    const int tid = threadIdx.x;
    const int n = blockIdx.y;
    const int l0 = blockIdx.x * TILE;
    const int Lnew = Lcur - d;

    // ---- stage the two input taps: X0[i][l]=src[l0+l], X1[i][l]=src[l0+l+d] ----
    const float* srcn = src + (size_t)n * CH * src_stride;
#pragma unroll
    for (int k = 0; k < (CH * TILE) / NTH; k++) {
        int idx = tid + k * NTH;
        int i = idx >> 7, l = idx & (TILE - 1);
        int p0 = l0 + l;
        int p1 = p0 + d;
        sm[OFF_X0 + idx] = (p0 < Lcur) ? srcn[(size_t)i * src_stride + p0] : 0.f;
        sm[OFF_X1 + idx] = (p1 < Lcur) ? srcn[(size_t)i * src_stride + p1] : 0.f;
    }
    __syncthreads();

    const int lt = (tid & 31) * 4;   // 4 consecutive positions; warp spans the tile
    const int ot = (tid >> 5) * 4;   // 4 consecutive output channels; uniform per warp

    // ================= phase 1: dilated conv (64x64x2) + gated activation =================
    float acc[4][4];
#pragma unroll
    for (int a = 0; a < 4; a++)
#pragma unroll
        for (int b = 0; b < 4; b++) acc[a][b] = 0.f;

#pragma unroll 4
    for (int ii = 0; ii < CH; ii += 2) {
        float xa0[4], xb0[4], xa1[4], xb1[4];
        *(float4*)xa0 = *(const float4*)(sm + OFF_X0 + ii * TILE + lt);
        *(float4*)xb0 = *(const float4*)(sm + OFF_X1 + ii * TILE + lt);
        *(float4*)xa1 = *(const float4*)(sm + OFF_X0 + (ii + 1) * TILE + lt);
        *(float4*)xb1 = *(const float4*)(sm + OFF_X1 + (ii + 1) * TILE + lt);
#pragma unroll
        for (int oo = 0; oo < 4; oo++) {
            // Wd layout (Cout, Cin, 2): [i t0, i t1, i+1 t0, i+1 t1] = one float4
            const float4 w = __ldg((const float4*)(Wd + (ot + oo) * (2 * CH) + ii * 2));
#pragma unroll
            for (int ll = 0; ll < 4; ll++)
                acc[oo][ll] += w.x * xa0[ll] + w.y * xb0[ll]
                             + w.z * xa1[ll] + w.w * xb1[ll];
        }
    }
    // gated activation -> G[o][l]
#pragma unroll
    for (int oo = 0; oo < 4; oo++) {
        float g[4];
#pragma unroll
        for (int ll = 0; ll < 4; ll++) g[ll] = gated(acc[oo][ll]);
        *(float4*)(sm + OFF_G + (ot + oo) * TILE + lt) = *(float4*)g;
    }
    __syncthreads();

    // ================= phase 2a: residual 1x1 conv + residual add =================
    float r[4][4];
#pragma unroll
    for (int oo = 0; oo < 4; oo++) {
        // init with residual: out[:, :, -Lnew:] == tap-1 tile
        *(float4*)r[oo] = *(const float4*)(sm + OFF_X1 + (ot + oo) * TILE + lt);
    }

#pragma unroll 4
    for (int ii = 0; ii < CH; ii += 4) {
        float g0[4], g1[4], g2[4], g3[4];
        *(float4*)g0 = *(const float4*)(sm + OFF_G + (ii + 0) * TILE + lt);
        *(float4*)g1 = *(const float4*)(sm + OFF_G + (ii + 1) * TILE + lt);
        *(float4*)g2 = *(const float4*)(sm + OFF_G + (ii + 2) * TILE + lt);
        *(float4*)g3 = *(const float4*)(sm + OFF_G + (ii + 3) * TILE + lt);
#pragma unroll
        for (int oo = 0; oo < 4; oo++) {
            const float4 w = __ldg((const float4*)(Wr + (ot + oo) * CH + ii));
#pragma unroll
            for (int ll = 0; ll < 4; ll++)
                r[oo][ll] += w.x * g0[ll] + w.y * g1[ll]
                           + w.z * g2[ll] + w.w * g3[ll];
        }
    }
    // direct coalesced store of residual output (warp-contiguous per row)
#pragma unroll
    for (int oo = 0; oo < 4; oo++) {
        float* drow = dst + ((size_t)n * CH + (ot + oo)) * dst_stride;
#pragma unroll
        for (int ll = 0; ll < 4; ll++) {
            int p = l0 + lt + ll;
            if (p < Lnew) drow[p] = r[oo][ll];
        }
    }

    // ================= phase 2b: skip 1x1 conv (128x64), two passes of 4 ch =================
    const int st = (tid >> 5) * 8;
#pragma unroll
    for (int half = 0; half < 2; half++) {
        float sk[4][4];
#pragma unroll
        for (int a = 0; a < 4; a++)
#pragma unroll
            for (int b = 0; b < 4; b++) sk[a][b] = 0.f;

#pragma unroll 4
        for (int ii = 0; ii < CH; ii += 4) {
            float g0[4], g1[4], g2[4], g3[4];
            *(float4*)g0 = *(const float4*)(sm + OFF_G + (ii + 0) * TILE + lt);
            *(float4*)g1 = *(const float4*)(sm + OFF_G + (ii + 1) * TILE + lt);
            *(float4*)g2 = *(const float4*)(sm + OFF_G + (ii + 2) * TILE + lt);
            *(float4*)g3 = *(const float4*)(sm + OFF_G + (ii + 3) * TILE + lt);
#pragma unroll
            for (int ss = 0; ss < 4; ss++) {
                const float4 w = __ldg((const float4*)(Ws + (st + half * 4 + ss) * CH + ii));
#pragma unroll
                for (int ll = 0; ll < 4; ll++)
                    sk[ss][ll] += w.x * g0[ll] + w.y * g1[ll]
                                + w.z * g2[ll] + w.w * g3[ll];
            }
        }
        // skip accumulation directly in global (one writer per element per launch)
#pragma unroll
        for (int ss = 0; ss < 4; ss++) {
            float* srow = skip + ((size_t)n * SCH + (st + half * 4 + ss)) * L_OUT;
            if (is_first) {
#pragma unroll
                for (int ll = 0; ll < 4; ll++) {
                    int p = l0 + lt + ll;
                    int j = p - skip_off;
                    if (p < Lnew && j >= 0) srow[j] = sk[ss][ll];
                }
            } else {
#pragma unroll
                for (int ll = 0; ll < 4; ll++) {
                    int p = l0 + lt + ll;
                    int j = p - skip_off;
                    if (p < Lnew && j >= 0) srow[j] += sk[ss][ll];
                }
            }
        }
    }
}

extern "C" void kernel_launch(void* const* d_in, const int* in_sizes, int n_in,
                              void* d_out, int out_size)
{
    const float* x  = (const float*)d_in[0];  // (16, 64, 8192)
    const float* Wd = (const float*)d_in[1];  // (16, 64, 64, 2)
    const float* Wr = (const float*)d_in[2];  // (16, 64, 64)
    const float* Ws = (const float*)d_in[3];  // (16, 128, 64)

    float* out  = (float*)d_out;                                   // (16, 64, 7682)
    float* skip = (float*)d_out + (size_t)N_BATCH * CH * L_OUT;    // (16, 128, 7682)

    float *bufA = nullptr, *bufB = nullptr;
    cudaGetSymbolAddress((void**)&bufA, g_bufA);
    cudaGetSymbolAddress((void**)&bufB, g_bufB);
    cudaFuncSetAttribute(wavenet_block_kernel,
                         cudaFuncAttributeMaxDynamicSharedMemorySize,
                         SMEM_FLOATS * (int)sizeof(float));

    const int dil[NUM_BLOCKS] = {1, 2, 4, 8, 16, 32, 64, 128,
                                 1, 2, 4, 8, 16, 32, 64, 128};

    const float* src = x;
    int src_stride = L_IN;
    int Lcur = L_IN;

    for (int i = 0; i < NUM_BLOCKS; i++) {
        int d = dil[i];
        int Lnew = Lcur - d;
        float* dst;
        int dst_stride;
        if (i == NUM_BLOCKS - 1) { dst = out; dst_stride = L_OUT; }
        else                     { dst = (i & 1) ? bufB : bufA; dst_stride = L_IN; }

        dim3 grid((Lnew + TILE - 1) / TILE, N_BATCH);
        wavenet_block_kernel<<<grid, NTH, SMEM_FLOATS * sizeof(float)>>>(
            src, src_stride, dst, dst_stride,
            Wd + (size_t)i * CH * CH * 2,
            Wr + (size_t)i * CH * CH,
            Ws + (size_t)i * SCH * CH,
            skip, Lcur, d, Lnew - L_OUT, (i == 0) ? 1 : 0);

        src = dst;
        src_stride = dst_stride;
        Lcur = Lnew;
    }
}